// round 4
// baseline (speedup 1.0000x reference)
#include <cuda_runtime.h>
#include <cuda_bf16.h>
#include <stdint.h>

#define BQ 1024
#define DD 512
#define NP 65536
#define NSTEPS 10
#define KSPLIT 8

// ---------------- scratch (device globals; no allocation allowed) ----------------
__device__ float g_S[(size_t)BQ * NP];                 // 268 MB sims matrix
__device__ float g_patt[(size_t)NP * DD];              // tf32-pre-rounded patterns
__device__ float g_state[2][BQ * DD];                  // ping-pong state
__device__ float g_rm[BQ];                             // row max
__device__ float g_rl[BQ];                             // row sum exp
__device__ float g_energy[(NSTEPS + 1) * BQ];          // energy trajectory
__device__ float g_part[KSPLIT][BQ * DD];              // GEMM2 split-K partials

// ---------------- helpers ----------------
__device__ __forceinline__ void cp_async16(void* smem_dst, const void* gmem_src) {
    unsigned d = (unsigned)__cvta_generic_to_shared(smem_dst);
    asm volatile("cp.async.cg.shared.global [%0], [%1], 16;\n" ::"r"(d), "l"(gmem_src));
}
__device__ __forceinline__ void cp_commit() { asm volatile("cp.async.commit_group;\n"); }

__device__ __forceinline__ uint32_t f2tf32(float f) {
    uint32_t r;
    asm("cvt.rna.tf32.f32 %0, %1;" : "=r"(r) : "f"(f));
    return r;
}
__device__ __forceinline__ float f2tf32f(float f) {
    uint32_t r = f2tf32(f);
    return __uint_as_float(r);
}

// =================================================================
// Pre-round patterns to tf32 (once per launch; removes cvt from GEMM hot loops)
// =================================================================
__global__ __launch_bounds__(256) void pat_round_kernel(const float* __restrict__ pat) {
    size_t i = ((size_t)blockIdx.x * 256 + threadIdx.x) * 4;
    float4 v = *(const float4*)(pat + i);
    v.x = f2tf32f(v.x);
    v.y = f2tf32f(v.y);
    v.z = f2tf32f(v.z);
    v.w = f2tf32f(v.w);
    *(float4*)(g_patt + i) = v;
}

// =================================================================
// GEMM1: S[m][n] = sum_d state[m][d] * P[n][d]   (tf32 mma, fp32 acc)
// BM=128, BN=128, BK=16, 256 threads (8 warps: 2 x 4)
// =================================================================
#define G1_BK 16
#define G1_LD 20   // padded smem stride (floats)

__global__ __launch_bounds__(256, 1) void gemm1_kernel(int cur) {
    __shared__ float As[2][128 * G1_LD];
    __shared__ float Bs[2][128 * G1_LD];

    const float* __restrict__ state = g_state[cur];
    const float* __restrict__ pat = g_patt;
    const int m0 = blockIdx.y * 128;
    const int n0 = blockIdx.x * 128;
    const int tid = threadIdx.x;
    const int wid = tid >> 5, lane = tid & 31;
    const int wm = wid >> 2, wn = wid & 3;   // warp tile: 64(M) x 32(N)
    const int g = lane >> 2, c = lane & 3;

    float acc[4][4][4];
#pragma unroll
    for (int i = 0; i < 4; i++)
#pragma unroll
        for (int j = 0; j < 4; j++)
#pragma unroll
            for (int r = 0; r < 4; r++) acc[i][j][r] = 0.f;

#define G1_STAGE(bufi, ksi)                                                            \
    {                                                                                  \
        int k0s = (ksi)*G1_BK;                                                         \
        _Pragma("unroll") for (int i = 0; i < 2; i++) {                                \
            int idx = tid + i * 256;                                                   \
            int row = idx >> 2, c4 = idx & 3;                                          \
            cp_async16(&As[bufi][row * G1_LD + c4 * 4],                                \
                       state + (size_t)(m0 + row) * DD + k0s + c4 * 4);                \
            cp_async16(&Bs[bufi][row * G1_LD + c4 * 4],                                \
                       pat + (size_t)(n0 + row) * DD + k0s + c4 * 4);                  \
        }                                                                              \
        cp_commit();                                                                   \
    }

    G1_STAGE(0, 0);
    const int NS = DD / G1_BK;  // 32
    for (int ks = 0; ks < NS; ks++) {
        int buf = ks & 1;
        if (ks + 1 < NS) {
            G1_STAGE(buf ^ 1, ks + 1);
            asm volatile("cp.async.wait_group 1;\n");
        } else {
            asm volatile("cp.async.wait_group 0;\n");
        }
        __syncthreads();
        const float* Ab = As[buf];
        const float* Bb = Bs[buf];
#pragma unroll
        for (int kk = 0; kk < 2; kk++) {
            uint32_t af[4][4], bfr[4][2];
#pragma unroll
            for (int mi = 0; mi < 4; mi++) {
                int r0 = wm * 64 + mi * 16 + g;
                int col = kk * 8 + c;
                af[mi][0] = f2tf32(Ab[r0 * G1_LD + col]);
                af[mi][1] = f2tf32(Ab[(r0 + 8) * G1_LD + col]);
                af[mi][2] = f2tf32(Ab[r0 * G1_LD + col + 4]);
                af[mi][3] = f2tf32(Ab[(r0 + 8) * G1_LD + col + 4]);
            }
#pragma unroll
            for (int ni = 0; ni < 4; ni++) {
                int nr = wn * 32 + ni * 8 + g;
                int col = kk * 8 + c;
                bfr[ni][0] = __float_as_uint(Bb[nr * G1_LD + col]);       // pre-rounded
                bfr[ni][1] = __float_as_uint(Bb[nr * G1_LD + col + 4]);
            }
#pragma unroll
            for (int mi = 0; mi < 4; mi++)
#pragma unroll
                for (int ni = 0; ni < 4; ni++) {
                    asm volatile(
                        "mma.sync.aligned.m16n8k8.row.col.f32.tf32.tf32.f32 "
                        "{%0,%1,%2,%3}, {%4,%5,%6,%7}, {%8,%9}, {%0,%1,%2,%3};\n"
                        : "+f"(acc[mi][ni][0]), "+f"(acc[mi][ni][1]),
                          "+f"(acc[mi][ni][2]), "+f"(acc[mi][ni][3])
                        : "r"(af[mi][0]), "r"(af[mi][1]), "r"(af[mi][2]), "r"(af[mi][3]),
                          "r"(bfr[ni][0]), "r"(bfr[ni][1]));
                }
        }
        __syncthreads();
    }

    // epilogue
#pragma unroll
    for (int mi = 0; mi < 4; mi++) {
        int r0 = m0 + wm * 64 + mi * 16 + g;
#pragma unroll
        for (int ni = 0; ni < 4; ni++) {
            int ccol = n0 + wn * 32 + ni * 8 + c * 2;
            float2 v0 = make_float2(acc[mi][ni][0], acc[mi][ni][1]);
            float2 v1 = make_float2(acc[mi][ni][2], acc[mi][ni][3]);
            *(float2*)&g_S[(size_t)r0 * NP + ccol] = v0;
            *(float2*)&g_S[(size_t)(r0 + 8) * NP + ccol] = v1;
        }
    }
}

// =================================================================
// Reduce: per row m — rowmax, sumexp, energy. 1 block/row, 512 threads.
// =================================================================
__global__ __launch_bounds__(512) void reduce_kernel(int cur, int step) {
    const int row = blockIdx.x;
    const int tid = threadIdx.x;
    const int lane = tid & 31, wid = tid >> 5;
    const float* __restrict__ Srow = g_S + (size_t)row * NP;
    const float* __restrict__ state = g_state[cur];

    __shared__ float red[16];

    // pass 1: max
    float m = -3.4e38f;
    for (int k = tid; k < NP; k += 512) m = fmaxf(m, Srow[k]);
#pragma unroll
    for (int o = 16; o; o >>= 1) m = fmaxf(m, __shfl_xor_sync(0xffffffffu, m, o));
    if (lane == 0) red[wid] = m;
    __syncthreads();
    float mfull = red[0];
#pragma unroll
    for (int i = 1; i < 16; i++) mfull = fmaxf(mfull, red[i]);
    __syncthreads();

    // pass 2: sum exp
    float l = 0.f;
    for (int k = tid; k < NP; k += 512) l += __expf(Srow[k] - mfull);
#pragma unroll
    for (int o = 16; o; o >>= 1) l += __shfl_xor_sync(0xffffffffu, l, o);
    if (lane == 0) red[wid] = l;
    __syncthreads();
    float lfull = 0.f;
#pragma unroll
    for (int i = 0; i < 16; i++) lfull += red[i];
    __syncthreads();

    // state squared-norm (512 threads, 512 elems)
    float v = state[(size_t)row * DD + tid];
    float ss = v * v;
#pragma unroll
    for (int o = 16; o; o >>= 1) ss += __shfl_xor_sync(0xffffffffu, ss, o);
    if (lane == 0) red[wid] = ss;
    __syncthreads();
    float ssfull = 0.f;
#pragma unroll
    for (int i = 0; i < 16; i++) ssfull += red[i];

    if (tid == 0) {
        g_rm[row] = mfull;
        g_rl[row] = lfull;
        g_energy[step * BQ + row] = -(mfull + logf(lfull)) + 0.5f * ssfull;
    }
}

// =================================================================
// GEMM2 (tf32): part[z][m][j] = sum_{k in chunk z} exp(S[m][k]-rm[m]) * P[k][j]
// BM=64, BJ=128, BK=16. grid (4, 16, KSPLIT), 256 threads (8 warps 2x4).
// A = exp weights (tf32-rounded at staging), B = patterns [k][j] (pre-rounded).
// =================================================================
#define G2_LDA 20    // float stride for As rows (16 + pad)
#define G2_LDB 132   // float stride for Bs rows (128 + pad)

__global__ __launch_bounds__(256, 4) void gemm2_kernel() {
    __shared__ float As[64 * G2_LDA];
    __shared__ float Bs[16 * G2_LDB];
    __shared__ float rms[64];

    const float* __restrict__ pat = g_patt;
    const int j0 = blockIdx.x * 128;
    const int m0 = blockIdx.y * 64;
    const int split = blockIdx.z;
    const int tid = threadIdx.x;
    const int wid = tid >> 5, lane = tid & 31;
    const int wm = wid >> 2, wj = wid & 3;  // warp tile 32(M) x 32(J)
    const int g = lane >> 2, c = lane & 3;

    if (tid < 64) rms[tid] = g_rm[m0 + tid];
    __syncthreads();

    float acc[2][4][4];
#pragma unroll
    for (int i = 0; i < 2; i++)
#pragma unroll
        for (int j = 0; j < 4; j++)
#pragma unroll
            for (int r = 0; r < 4; r++) acc[i][j][r] = 0.f;

    const int a_row = tid >> 2, a_c4 = tid & 3;   // A stage: 1 float4/thread
    const float rm_mine = rms[a_row];

    const int kbase = split * (NP / KSPLIT);
    const int NIT = (NP / KSPLIT) / 16;  // 512
    for (int ks = 0; ks < NIT; ks++) {
        int k0 = kbase + ks * 16;
        // stage A: 64x16 fp32 -> exp -> tf32-rounded float
        {
            float4 v = *(const float4*)(g_S + (size_t)(m0 + a_row) * NP + k0 + a_c4 * 4);
            v.x = f2tf32f(__expf(v.x - rm_mine));
            v.y = f2tf32f(__expf(v.y - rm_mine));
            v.z = f2tf32f(__expf(v.z - rm_mine));
            v.w = f2tf32f(__expf(v.w - rm_mine));
            *(float4*)(&As[a_row * G2_LDA + a_c4 * 4]) = v;
        }
        // stage B: 16 x 128 (already tf32-rounded) — 2 float4/thread
#pragma unroll
        for (int i = 0; i < 2; i++) {
            int idx = tid + i * 256;
            int row = idx >> 5, c4 = idx & 31;
            float4 v = *(const float4*)(pat + (size_t)(k0 + row) * DD + j0 + c4 * 4);
            *(float4*)(&Bs[row * G2_LDB + c4 * 4]) = v;
        }
        __syncthreads();

#pragma unroll
        for (int kk = 0; kk < 2; kk++) {
            uint32_t af[2][4], bfr[4][2];
#pragma unroll
            for (int mi = 0; mi < 2; mi++) {
                int r = wm * 32 + mi * 16 + g;
                int col = kk * 8 + c;
                af[mi][0] = __float_as_uint(As[r * G2_LDA + col]);
                af[mi][1] = __float_as_uint(As[(r + 8) * G2_LDA + col]);
                af[mi][2] = __float_as_uint(As[r * G2_LDA + col + 4]);
                af[mi][3] = __float_as_uint(As[(r + 8) * G2_LDA + col + 4]);
            }
#pragma unroll
            for (int ji = 0; ji < 4; ji++) {
                int jc = wj * 32 + ji * 8 + g;
                int kr = kk * 8 + c;
                bfr[ji][0] = __float_as_uint(Bs[kr * G2_LDB + jc]);
                bfr[ji][1] = __float_as_uint(Bs[(kr + 4) * G2_LDB + jc]);
            }
#pragma unroll
            for (int mi = 0; mi < 2; mi++)
#pragma unroll
                for (int ji = 0; ji < 4; ji++) {
                    asm volatile(
                        "mma.sync.aligned.m16n8k8.row.col.f32.tf32.tf32.f32 "
                        "{%0,%1,%2,%3}, {%4,%5,%6,%7}, {%8,%9}, {%0,%1,%2,%3};\n"
                        : "+f"(acc[mi][ji][0]), "+f"(acc[mi][ji][1]),
                          "+f"(acc[mi][ji][2]), "+f"(acc[mi][ji][3])
                        : "r"(af[mi][0]), "r"(af[mi][1]), "r"(af[mi][2]), "r"(af[mi][3]),
                          "r"(bfr[ji][0]), "r"(bfr[ji][1]));
                }
        }
        __syncthreads();
    }

    float* __restrict__ outp = g_part[split];
#pragma unroll
    for (int mi = 0; mi < 2; mi++) {
        int r0 = m0 + wm * 32 + mi * 16 + g;
#pragma unroll
        for (int ji = 0; ji < 4; ji++) {
            int col = j0 + wj * 32 + ji * 8 + 2 * c;
            float2 v0 = make_float2(acc[mi][ji][0], acc[mi][ji][1]);
            float2 v1 = make_float2(acc[mi][ji][2], acc[mi][ji][3]);
            *(float2*)&outp[(size_t)r0 * DD + col] = v0;
            *(float2*)&outp[(size_t)(r0 + 8) * DD + col] = v1;
        }
    }
}

// =================================================================
// Combine: new_state = (sum of split partials) / l
// =================================================================
__global__ __launch_bounds__(256) void combine_kernel(int nxt) {
    int i = blockIdx.x * 256 + threadIdx.x;
    float s = 0.f;
#pragma unroll
    for (int p = 0; p < KSPLIT; p++) s += g_part[p][i];
    g_state[nxt][i] = s / g_rl[i >> 9];
}

// =================================================================
// Init + pack
// =================================================================
__global__ __launch_bounds__(256) void init_state_kernel(const float* __restrict__ q) {
    int i = blockIdx.x * 256 + threadIdx.x;
    g_state[0][i] = q[i];
}

__global__ __launch_bounds__(256) void pack_kernel(float* __restrict__ out, int finalbuf, int total) {
    int i = blockIdx.x * 256 + threadIdx.x;
    if (i >= total) return;
    if (i < BQ * DD) {
        out[i] = g_state[finalbuf][i];
    } else {
        int e = i - BQ * DD;
        if (e < (NSTEPS + 1) * BQ) out[i] = g_energy[e];
    }
}

// =================================================================
// launch
// =================================================================
extern "C" void kernel_launch(void* const* d_in, const int* in_sizes, int n_in,
                              void* d_out, int out_size) {
    const float* query = (const float*)d_in[0];
    const float* patterns = (const float*)d_in[1];
    if (n_in >= 2 && in_sizes[0] != BQ * DD) {  // defensive: identify by size
        const float* t = query;
        query = patterns;
        patterns = t;
    }
    float* out = (float*)d_out;

    init_state_kernel<<<(BQ * DD) / 256, 256>>>(query);
    pat_round_kernel<<<(NP * DD) / (256 * 4), 256>>>(patterns);

    dim3 g1grid(NP / 128, BQ / 128);         // (512, 8)
    dim3 g2grid(DD / 128, BQ / 64, KSPLIT);  // (4, 16, 8)

    for (int t = 0; t < NSTEPS; t++) {
        int cur = t & 1;
        gemm1_kernel<<<g1grid, 256>>>(cur);
        reduce_kernel<<<BQ, 512>>>(cur, t);
        gemm2_kernel<<<g2grid, 256>>>();
        combine_kernel<<<(BQ * DD) / 256, 256>>>(cur ^ 1);
    }
    // final energy from state_10 (lives in buffer 0 after 10 steps)
    gemm1_kernel<<<g1grid, 256>>>(0);
    reduce_kernel<<<BQ, 512>>>(0, NSTEPS);

    int total = out_size;
    pack_kernel<<<(total + 255) / 256, 256>>>(out, 0, total);
}

// round 6
// speedup vs baseline: 1.4192x; 1.4192x over previous
#include <cuda_runtime.h>
#include <stdint.h>

#define BQ 1024
#define DD 512
#define NP 65536
#define NSTEPS 10
#define KSPLIT 64

#define BM 128
#define BN 128
#define BK 32
#define LDK 36                       // padded float stride (4g+c -> all banks distinct)
#define STG (BM * LDK)               // floats per operand stage (4608)
#define NSTG 3
#define SMEM_BYTES (NSTG * 2 * STG * 4)  // 110592 B

// ---------------- scratch (device globals; no allocation allowed) ----------------
__device__ float g_S[(size_t)BQ * NP];             // sims, then exp(sims - rowmax) (tf32-rounded)
__device__ float g_patt[(size_t)NP * DD];          // tf32-rounded patterns [n][d]
__device__ float g_pattT[(size_t)DD * NP];         // tf32-rounded patterns transposed [d][n]
__device__ float g_state[BQ * DD];                 // fp32 state (output precision)
__device__ float g_state_r[BQ * DD];               // tf32-rounded state (GEMM1 A)
__device__ float g_rm[BQ];
__device__ float g_rl[BQ];
__device__ float g_energy[(NSTEPS + 1) * BQ];
__device__ float g_part[(size_t)KSPLIT * BQ * DD]; // GEMM2 split-K partials (128 MB)

// ---------------- helpers ----------------
__device__ __forceinline__ void cp_async16(void* smem_dst, const void* gmem_src) {
    unsigned d = (unsigned)__cvta_generic_to_shared(smem_dst);
    asm volatile("cp.async.cg.shared.global [%0], [%1], 16;\n" ::"r"(d), "l"(gmem_src));
}
__device__ __forceinline__ void cp_commit() { asm volatile("cp.async.commit_group;\n"); }

__device__ __forceinline__ uint32_t f2tf32(float f) {
    uint32_t r;
    asm("cvt.rna.tf32.f32 %0, %1;" : "=r"(r) : "f"(f));
    return r;
}
__device__ __forceinline__ float f2tf32f(float f) { return __uint_as_float(f2tf32(f)); }

// =================================================================
// Unified tf32 mma.sync GEMM: D[m0..+128][n0..+128] (+z split)
//   = sum_k A[m][k] * B[n][k],  A,B row-major k-contiguous, pre-rounded tf32.
// which=0: S = state_r * patt^T        (k over DD, z=1)
// which=1: part[z] = expS * pattT^T    (k over NP/KSPLIT per z)
// 256 threads, 8 warps (2x4), warp tile 64x32, 3-stage cp.async ring.
// =================================================================
__global__ __launch_bounds__(256, 2) void gemm_ms(int which) {
    extern __shared__ float sm[];

    const float *A, *B;
    float* D;
    size_t lda, ldb, ldd, dof;
    int nit;
    if (which == 0) {
        A = g_state_r; lda = DD;
        B = g_patt;    ldb = DD;
        D = g_S;       ldd = NP; dof = 0;
        nit = DD / BK;                      // 16
    } else {
        A = g_S;       lda = NP;
        B = g_pattT;   ldb = NP;
        D = g_part;    ldd = DD; dof = (size_t)BQ * DD;
        nit = (NP / KSPLIT) / BK;           // 32
    }

    const int tid = threadIdx.x;
    const int wid = tid >> 5, lane = tid & 31;
    const int wm = wid >> 2, wn = wid & 3;   // warp tile: 64(M) x 32(N)
    const int g = lane >> 2, c = lane & 3;
    const int m0 = blockIdx.y * BM;
    const int n0 = blockIdx.x * BN;
    const long kbase = (long)blockIdx.z * (NP / KSPLIT);  // 0 for gemm1

    // staging: A,B tiles 128 rows x 8 float4 each (1024 ops apiece, 4/thread)
    const int s_r = tid >> 3, s_c4 = tid & 7;  // base op for i=0 pattern below
    (void)s_r; (void)s_c4;

    auto stagef = [&](int buf, int it) {
        long kcol = kbase + (long)it * BK;
        float* As = sm + buf * (2 * STG);
        float* Bs = As + STG;
#pragma unroll
        for (int i = 0; i < 4; i++) {
            int op = tid + i * 256;
            int r = op >> 3, c4 = op & 7;
            cp_async16(&As[r * LDK + c4 * 4], A + (size_t)(m0 + r) * lda + kcol + c4 * 4);
        }
#pragma unroll
        for (int i = 0; i < 4; i++) {
            int op = tid + i * 256;
            int r = op >> 3, c4 = op & 7;
            cp_async16(&Bs[r * LDK + c4 * 4], B + (size_t)(n0 + r) * ldb + kcol + c4 * 4);
        }
    };

    float acc[4][4][4];
#pragma unroll
    for (int i = 0; i < 4; i++)
#pragma unroll
        for (int j = 0; j < 4; j++)
#pragma unroll
            for (int r = 0; r < 4; r++) acc[i][j][r] = 0.f;

    stagef(0, 0); cp_commit();
    stagef(1, 1); cp_commit();

    for (int s = 0; s < nit; s++) {
        asm volatile("cp.async.wait_group 1;\n");
        __syncthreads();
        if (s + 2 < nit) stagef((s + 2) % NSTG, s + 2);
        cp_commit();

        const float* As = sm + (s % NSTG) * (2 * STG);
        const float* Bs = As + STG;
#pragma unroll
        for (int kk = 0; kk < 4; kk++) {
            uint32_t af[4][4], bf[4][2];
            int col = kk * 8 + c;
#pragma unroll
            for (int mi = 0; mi < 4; mi++) {
                int r0 = wm * 64 + mi * 16 + g;
                af[mi][0] = __float_as_uint(As[r0 * LDK + col]);
                af[mi][1] = __float_as_uint(As[(r0 + 8) * LDK + col]);
                af[mi][2] = __float_as_uint(As[r0 * LDK + col + 4]);
                af[mi][3] = __float_as_uint(As[(r0 + 8) * LDK + col + 4]);
            }
#pragma unroll
            for (int ni = 0; ni < 4; ni++) {
                int nr = wn * 32 + ni * 8 + g;
                bf[ni][0] = __float_as_uint(Bs[nr * LDK + col]);
                bf[ni][1] = __float_as_uint(Bs[nr * LDK + col + 4]);
            }
#pragma unroll
            for (int mi = 0; mi < 4; mi++)
#pragma unroll
                for (int ni = 0; ni < 4; ni++) {
                    asm volatile(
                        "mma.sync.aligned.m16n8k8.row.col.f32.tf32.tf32.f32 "
                        "{%0,%1,%2,%3}, {%4,%5,%6,%7}, {%8,%9}, {%0,%1,%2,%3};\n"
                        : "+f"(acc[mi][ni][0]), "+f"(acc[mi][ni][1]),
                          "+f"(acc[mi][ni][2]), "+f"(acc[mi][ni][3])
                        : "r"(af[mi][0]), "r"(af[mi][1]), "r"(af[mi][2]), "r"(af[mi][3]),
                          "r"(bf[ni][0]), "r"(bf[ni][1]));
                }
        }
    }

    // epilogue: direct reg -> gmem
    float* Dp = D + (size_t)blockIdx.z * dof + (size_t)m0 * ldd + n0;
#pragma unroll
    for (int mi = 0; mi < 4; mi++) {
        int r0 = wm * 64 + mi * 16 + g;
#pragma unroll
        for (int ni = 0; ni < 4; ni++) {
            int col = wn * 32 + ni * 8 + c * 2;
            float2 v0 = make_float2(acc[mi][ni][0], acc[mi][ni][1]);
            float2 v1 = make_float2(acc[mi][ni][2], acc[mi][ni][3]);
            *(float2*)&Dp[(size_t)r0 * ldd + col] = v0;
            *(float2*)&Dp[(size_t)(r0 + 8) * ldd + col] = v1;
        }
    }
}

// =================================================================
// Pattern prep (once): tf32-round into g_patt, transpose into g_pattT
// =================================================================
__global__ __launch_bounds__(256) void pat_prep_kernel(const float* __restrict__ pat) {
    __shared__ float t[32][33];
    int n0 = blockIdx.x * 32, d0 = blockIdx.y * 32;
    int tx = threadIdx.x & 31, ty = threadIdx.x >> 5;  // 32 x 8
#pragma unroll
    for (int i = ty; i < 32; i += 8) {
        float v = f2tf32f(pat[(size_t)(n0 + i) * DD + d0 + tx]);
        g_patt[(size_t)(n0 + i) * DD + d0 + tx] = v;
        t[i][tx] = v;
    }
    __syncthreads();
#pragma unroll
    for (int i = ty; i < 32; i += 8)
        g_pattT[(size_t)(d0 + i) * NP + n0 + tx] = t[tx][i];
}

// =================================================================
// Reduce: rowmax, exp-writeback (tf32) + sumexp + energy
// =================================================================
__global__ __launch_bounds__(512) void reduce_kernel(int step) {
    const int row = blockIdx.x;
    const int tid = threadIdx.x;
    const int lane = tid & 31, wrp = tid >> 5;
    float4* S4 = (float4*)(g_S + (size_t)row * NP);
    __shared__ float red[16];

    float m = -3.4e38f;
    for (int k = tid; k < NP / 4; k += 512) {
        float4 v = S4[k];
        m = fmaxf(m, fmaxf(fmaxf(v.x, v.y), fmaxf(v.z, v.w)));
    }
#pragma unroll
    for (int o = 16; o; o >>= 1) m = fmaxf(m, __shfl_xor_sync(0xffffffffu, m, o));
    if (lane == 0) red[wrp] = m;
    __syncthreads();
    float mfull = red[0];
#pragma unroll
    for (int i = 1; i < 16; i++) mfull = fmaxf(mfull, red[i]);
    __syncthreads();

    float l = 0.f;
    for (int k = tid; k < NP / 4; k += 512) {
        float4 v = S4[k];
        float e0 = __expf(v.x - mfull), e1 = __expf(v.y - mfull);
        float e2 = __expf(v.z - mfull), e3 = __expf(v.w - mfull);
        l += (e0 + e1) + (e2 + e3);
        v.x = f2tf32f(e0); v.y = f2tf32f(e1); v.z = f2tf32f(e2); v.w = f2tf32f(e3);
        S4[k] = v;
    }
#pragma unroll
    for (int o = 16; o; o >>= 1) l += __shfl_xor_sync(0xffffffffu, l, o);
    if (lane == 0) red[wrp] = l;
    __syncthreads();
    float lfull = 0.f;
#pragma unroll
    for (int i = 0; i < 16; i++) lfull += red[i];
    __syncthreads();

    float v = g_state[(size_t)row * DD + tid];
    float ss = v * v;
#pragma unroll
    for (int o = 16; o; o >>= 1) ss += __shfl_xor_sync(0xffffffffu, ss, o);
    if (lane == 0) red[wrp] = ss;
    __syncthreads();
    float ssfull = 0.f;
#pragma unroll
    for (int i = 0; i < 16; i++) ssfull += red[i];

    if (tid == 0) {
        g_rm[row] = mfull;
        g_rl[row] = lfull;
        g_energy[step * BQ + row] = -(mfull + logf(lfull)) + 0.5f * ssfull;
    }
}

// =================================================================
// Combine: state = (sum of split partials) / l   (fp32 + tf32 copies)
// =================================================================
__global__ __launch_bounds__(256) void combine_kernel() {
    int i = blockIdx.x * 256 + threadIdx.x;
    float s = 0.f;
#pragma unroll
    for (int p = 0; p < KSPLIT; p++) s += g_part[(size_t)p * BQ * DD + i];
    float v = s / g_rl[i >> 9];
    g_state[i] = v;
    g_state_r[i] = f2tf32f(v);
}

__global__ __launch_bounds__(256) void init_state_kernel(const float* __restrict__ q) {
    int i = blockIdx.x * 256 + threadIdx.x;
    float v = q[i];
    g_state[i] = v;
    g_state_r[i] = f2tf32f(v);
}

__global__ __launch_bounds__(256) void pack_kernel(float* __restrict__ out, int total) {
    int i = blockIdx.x * 256 + threadIdx.x;
    if (i >= total) return;
    if (i < BQ * DD) {
        out[i] = g_state[i];
    } else {
        int e = i - BQ * DD;
        if (e < (NSTEPS + 1) * BQ) out[i] = g_energy[e];
    }
}

// =================================================================
// launch
// =================================================================
extern "C" void kernel_launch(void* const* d_in, const int* in_sizes, int n_in,
                              void* d_out, int out_size) {
    const float* query = (const float*)d_in[0];
    const float* patterns = (const float*)d_in[1];
    if (n_in >= 2 && in_sizes[0] != BQ * DD) {
        const float* t = query;
        query = patterns;
        patterns = t;
    }
    float* out = (float*)d_out;

    cudaFuncSetAttribute(gemm_ms, cudaFuncAttributeMaxDynamicSharedMemorySize, SMEM_BYTES);

    init_state_kernel<<<(BQ * DD) / 256, 256>>>(query);
    pat_prep_kernel<<<dim3(NP / 32, DD / 32), 256>>>(patterns);

    dim3 g1grid(NP / BN, BQ / BM, 1);        // (512, 8, 1)
    dim3 g2grid(DD / BN, BQ / BM, KSPLIT);   // (4, 8, 64)

    for (int t = 0; t < NSTEPS; t++) {
        gemm_ms<<<g1grid, 256, SMEM_BYTES>>>(0);
        reduce_kernel<<<BQ, 512>>>(t);
        gemm_ms<<<g2grid, 256, SMEM_BYTES>>>(1);
        combine_kernel<<<(BQ * DD) / 256, 256>>>();
    }
    gemm_ms<<<g1grid, 256, SMEM_BYTES>>>(0);
    reduce_kernel<<<BQ, 512>>>(NSTEPS);

    pack_kernel<<<(out_size + 255) / 256, 256>>>(out, out_size);
}

// round 8
// speedup vs baseline: 2.1311x; 1.5016x over previous
#include <cuda_runtime.h>
#include <stdint.h>

#define BQ 1024
#define DD 512
#define NP 65536
#define NSTEPS 10
#define KSPLIT 64

#define BM 128
#define BN 128
#define BK 32
#define PANEL_F 4096                      // floats per 128x32 panel
#define PANEL_B 16384                     // bytes per panel
#define NSTG 3
#define SMEM_BYTES (1024 + NSTG * 2 * PANEL_B)   // 99328 B -> 2 CTAs/SM

// ---------------- tiled global scratch (device globals; no allocation) ----------------
// panel layout: element (r, cl) of a [128 x 32] float panel lives at float index
//   swzf(r, cl) = r*32 + ((((cl>>2) ^ (r&7)) & 7) << 2) + (cl & 3)
__device__ float g_S_t[(size_t)8 * 2048 * PANEL_F];      // exp weights tiled [mblk][kstg]
__device__ float g_patt_t[(size_t)512 * 16 * PANEL_F];   // P tiled     [nblk][kstg]
__device__ float g_pattT_t[(size_t)4 * 2048 * PANEL_F];  // P^T tiled   [jblk][kstg]
__device__ float g_state_rt[(size_t)8 * 16 * PANEL_F];   // state tf32 tiled
__device__ float g_state[BQ * DD];                       // fp32 state (output)
__device__ float g_lpart[(size_t)BQ * (NP / BN)];        // [row][nblk] partial expsums
__device__ float g_rl[BQ];
__device__ float g_ssq[BQ];
__device__ float g_shift[BQ];                            // b = ||state|| (softmax shift)
__device__ float g_energy[(NSTEPS + 1) * BQ];
__device__ float g_part[(size_t)KSPLIT * BQ * DD];       // GEMM2 split-K partials

// ---------------- helpers ----------------
__device__ __forceinline__ uint32_t f2tf32(float f) {
    uint32_t r;
    asm("cvt.rna.tf32.f32 %0, %1;" : "=r"(r) : "f"(f));
    return r;
}
__device__ __forceinline__ float f2tf32f(float f) { return __uint_as_float(f2tf32(f)); }

__device__ __forceinline__ uint32_t swzf(uint32_t r, uint32_t cl) {
    return r * 32u + ((((cl >> 2) ^ r) & 7u) << 2) + (cl & 3u);
}

__device__ __forceinline__ void mbar_init(uint32_t addr, uint32_t cnt) {
    asm volatile("mbarrier.init.shared.b64 [%0], %1;" ::"r"(addr), "r"(cnt) : "memory");
}
__device__ __forceinline__ void mbar_expect_tx(uint32_t addr, uint32_t bytes) {
    asm volatile("mbarrier.arrive.expect_tx.shared.b64 _, [%0], %1;"
                 ::"r"(addr), "r"(bytes) : "memory");
}
__device__ __forceinline__ void mbar_wait(uint32_t addr, uint32_t parity) {
    asm volatile(
        "{\n\t.reg .pred P1;\n\t"
        "WAIT_%=:\n\t"
        "mbarrier.try_wait.parity.acquire.cta.shared::cta.b64 P1, [%0], %1, 0x989680;\n\t"
        "@!P1 bra WAIT_%=;\n\t"
        "}"
        ::"r"(addr), "r"(parity) : "memory");
}
__device__ __forceinline__ void bulk_g2s(uint32_t daddr, const void* src, uint32_t bytes,
                                         uint32_t mbar) {
    asm volatile(
        "cp.async.bulk.shared::cluster.global.mbarrier::complete_tx::bytes "
        "[%0], [%1], %2, [%3];"
        ::"r"(daddr), "l"(src), "r"(bytes), "r"(mbar) : "memory");
}

// =================================================================
// Unified tf32 mma.sync GEMM over tiled panels.
// which=0: S = state * P^T ; epilogue: exp(s - b), tf32-round, tiled store,
//          per-row tile sums of ROUNDED weights -> g_lpart[row][bx]
// which=1: part[z] = expS * P ; plain store
// =================================================================
__global__ __launch_bounds__(256, 2) void gemm_ms(int which) {
    extern __shared__ float sm[];
    const uint32_t sbase = (uint32_t)__cvta_generic_to_shared(sm);

    const float *A, *B;
    int nit;
    size_t kstg_tot, kb;
    if (which == 0) {
        A = g_state_rt; B = g_patt_t;
        kstg_tot = 16; kb = 0; nit = 16;
    } else {
        A = g_S_t; B = g_pattT_t;
        kstg_tot = 2048; kb = (size_t)blockIdx.z * 32; nit = 32;
    }

    const int tid = threadIdx.x;
    const int wid = tid >> 5, lane = tid & 31;
    const int wm = wid >> 2, wn = wid & 3;  // warp tile 64(M) x 32(N)
    const int g = lane >> 2, c = lane & 3;
    const int bx = blockIdx.x, by = blockIdx.y;

    if (tid == 0) {
#pragma unroll
        for (int b = 0; b < NSTG; b++) mbar_init(sbase + 8 * b, 1);
        asm volatile("fence.proxy.async.shared::cta;" ::: "memory");
    }
    __syncthreads();

    auto stage = [&](int u) {
        int b = u % NSTG;
        uint32_t mbar = sbase + 8 * b;
        uint32_t da = sbase + 1024 + b * (2 * PANEL_B);
        mbar_expect_tx(mbar, 2 * PANEL_B);
        bulk_g2s(da, A + ((size_t)by * kstg_tot + kb + u) * PANEL_F, PANEL_B, mbar);
        bulk_g2s(da + PANEL_B, B + ((size_t)bx * kstg_tot + kb + u) * PANEL_F, PANEL_B, mbar);
    };

    if (tid == 0) {
        stage(0); stage(1); stage(2);
    }

    float acc[4][4][4];
#pragma unroll
    for (int i = 0; i < 4; i++)
#pragma unroll
        for (int j = 0; j < 4; j++)
#pragma unroll
            for (int r = 0; r < 4; r++) acc[i][j][r] = 0.f;

    for (int s = 0; s < nit; s++) {
        int b = s % NSTG;
        mbar_wait(sbase + 8 * b, (s / NSTG) & 1);
        const float* As = sm + 256 + b * (2 * PANEL_F);
        const float* Bs = As + PANEL_F;
#pragma unroll
        for (int kk = 0; kk < 4; kk++) {
            const int x0 = (((2 * kk) ^ g) & 7) << 2;
            const int x1 = (((2 * kk + 1) ^ g) & 7) << 2;
            uint32_t af[4][4], bf[4][2];
#pragma unroll
            for (int mi = 0; mi < 4; mi++) {
                int r0 = wm * 64 + mi * 16 + g;
                af[mi][0] = __float_as_uint(As[r0 * 32 + x0 + c]);
                af[mi][1] = __float_as_uint(As[(r0 + 8) * 32 + x0 + c]);
                af[mi][2] = __float_as_uint(As[r0 * 32 + x1 + c]);
                af[mi][3] = __float_as_uint(As[(r0 + 8) * 32 + x1 + c]);
            }
#pragma unroll
            for (int ni = 0; ni < 4; ni++) {
                int nr = wn * 32 + ni * 8 + g;
                bf[ni][0] = __float_as_uint(Bs[nr * 32 + x0 + c]);
                bf[ni][1] = __float_as_uint(Bs[nr * 32 + x1 + c]);
            }
#pragma unroll
            for (int mi = 0; mi < 4; mi++)
#pragma unroll
                for (int ni = 0; ni < 4; ni++) {
                    asm volatile(
                        "mma.sync.aligned.m16n8k8.row.col.f32.tf32.tf32.f32 "
                        "{%0,%1,%2,%3}, {%4,%5,%6,%7}, {%8,%9}, {%0,%1,%2,%3};\n"
                        : "+f"(acc[mi][ni][0]), "+f"(acc[mi][ni][1]),
                          "+f"(acc[mi][ni][2]), "+f"(acc[mi][ni][3])
                        : "r"(af[mi][0]), "r"(af[mi][1]), "r"(af[mi][2]), "r"(af[mi][3]),
                          "r"(bf[ni][0]), "r"(bf[ni][1]));
                }
        }
        __syncthreads();
        if (tid == 0 && s + NSTG < nit) stage(s + NSTG);
    }

    if (which == 0) {
        // ---- epilogue: exp(s - b) + tf32 round + tiled store + row sums ----
        float* Sp = g_S_t + ((size_t)by * 2048 + bx * 4 + wn) * PANEL_F;
        float* lsum = sm + 256;  // [128][4], buffers are dead now
#pragma unroll
        for (int mi = 0; mi < 4; mi++) {
            int r0 = wm * 64 + mi * 16 + g;
            float b0 = g_shift[by * BM + r0];
            float b1 = g_shift[by * BM + r0 + 8];
            float s0 = 0.f, s1 = 0.f;
#pragma unroll
            for (int ni = 0; ni < 4; ni++) {
                int cl = ni * 8 + 2 * c;
                float e00 = f2tf32f(__expf(acc[mi][ni][0] - b0));
                float e01 = f2tf32f(__expf(acc[mi][ni][1] - b0));
                float e10 = f2tf32f(__expf(acc[mi][ni][2] - b1));
                float e11 = f2tf32f(__expf(acc[mi][ni][3] - b1));
                s0 += e00 + e01;
                s1 += e10 + e11;
                *(float2*)&Sp[swzf(r0, cl)] = make_float2(e00, e01);
                *(float2*)&Sp[swzf(r0 + 8, cl)] = make_float2(e10, e11);
            }
            s0 += __shfl_xor_sync(0xffffffffu, s0, 1);
            s0 += __shfl_xor_sync(0xffffffffu, s0, 2);
            s1 += __shfl_xor_sync(0xffffffffu, s1, 1);
            s1 += __shfl_xor_sync(0xffffffffu, s1, 2);
            if (c == 0) {
                lsum[r0 * 4 + wn] = s0;
                lsum[(r0 + 8) * 4 + wn] = s1;
            }
        }
        __syncthreads();
        if (tid < 128) {
            float tot = lsum[tid * 4 + 0] + lsum[tid * 4 + 1] +
                        lsum[tid * 4 + 2] + lsum[tid * 4 + 3];
            g_lpart[(size_t)(by * BM + tid) * (NP / BN) + bx] = tot;
        }
    } else {
        float* Dp = g_part + (size_t)blockIdx.z * (BQ * DD) +
                    (size_t)(by * BM) * DD + bx * BN;
#pragma unroll
        for (int mi = 0; mi < 4; mi++) {
            int r0 = wm * 64 + mi * 16 + g;
#pragma unroll
            for (int ni = 0; ni < 4; ni++) {
                int col = wn * 32 + ni * 8 + c * 2;
                float2 v0 = make_float2(acc[mi][ni][0], acc[mi][ni][1]);
                float2 v1 = make_float2(acc[mi][ni][2], acc[mi][ni][3]);
                *(float2*)&Dp[(size_t)r0 * DD + col] = v0;
                *(float2*)&Dp[(size_t)(r0 + 8) * DD + col] = v1;
            }
        }
    }
}

// =================================================================
// Pattern prep (once): tf32-round into tiled g_patt_t and g_pattT_t
// =================================================================
__global__ __launch_bounds__(256) void pat_prep_kernel(const float* __restrict__ pat) {
    __shared__ float t[32][33];
    int n0 = blockIdx.x * 32, d0 = blockIdx.y * 32;
    int tx = threadIdx.x & 31, ty = threadIdx.x >> 5;  // 32 x 8
#pragma unroll
    for (int i = ty; i < 32; i += 8) {
        int n = n0 + i;
        float v = f2tf32f(pat[(size_t)n * DD + d0 + tx]);
        g_patt_t[((size_t)(n >> 7) * 16 + (d0 >> 5)) * PANEL_F + swzf(n & 127, tx)] = v;
        t[i][tx] = v;
    }
    __syncthreads();
#pragma unroll
    for (int i = ty; i < 32; i += 8) {
        int d = d0 + i;
        g_pattT_t[((size_t)(d >> 7) * 2048 + (n0 >> 5)) * PANEL_F + swzf(d & 127, tx)] =
            t[tx][i];
    }
}

// =================================================================
// lsum + energy: l[row] = sum of 512 tile sums; energy = -(b + log l) + 0.5 ssq
// =================================================================
__global__ __launch_bounds__(256) void lsum_energy_kernel(int step) {
    const int row = blockIdx.x;
    const int tid = threadIdx.x;
    const int lane = tid & 31, wrp = tid >> 5;
    __shared__ float red[8];
    float s = 0.f;
    for (int k = tid; k < NP / BN; k += 256) s += g_lpart[(size_t)row * (NP / BN) + k];
#pragma unroll
    for (int o = 16; o; o >>= 1) s += __shfl_xor_sync(0xffffffffu, s, o);
    if (lane == 0) red[wrp] = s;
    __syncthreads();
    if (tid == 0) {
        float l = 0.f;
#pragma unroll
        for (int i = 0; i < 8; i++) l += red[i];
        g_rl[row] = l;
        g_energy[step * BQ + row] = -(g_shift[row] + logf(l)) + 0.5f * g_ssq[row];
    }
}

// =================================================================
// Combine: state = (sum of split partials) / l; fp32 + tiled tf32; ssq + shift
// =================================================================
__global__ __launch_bounds__(512) void combine_kernel() {
    const int row = blockIdx.x;
    const int d = threadIdx.x;
    const int lane = d & 31, wrp = d >> 5;
    __shared__ float red[16];
    float s = 0.f;
#pragma unroll
    for (int z = 0; z < KSPLIT; z++) s += g_part[(size_t)z * (BQ * DD) + (size_t)row * DD + d];
    float v = s / g_rl[row];
    g_state[(size_t)row * DD + d] = v;
    g_state_rt[((size_t)(row >> 7) * 16 + (d >> 5)) * PANEL_F + swzf(row & 127, d & 31)] =
        f2tf32f(v);
    float ss = v * v;
#pragma unroll
    for (int o = 16; o; o >>= 1) ss += __shfl_xor_sync(0xffffffffu, ss, o);
    if (lane == 0) red[wrp] = ss;
    __syncthreads();
    if (d == 0) {
        float tot = 0.f;
#pragma unroll
        for (int i = 0; i < 16; i++) tot += red[i];
        g_ssq[row] = tot;
        g_shift[row] = sqrtf(tot);
    }
}

__global__ __launch_bounds__(512) void init_state_kernel(const float* __restrict__ q) {
    const int row = blockIdx.x;
    const int d = threadIdx.x;
    const int lane = d & 31, wrp = d >> 5;
    __shared__ float red[16];
    float v = q[(size_t)row * DD + d];
    g_state[(size_t)row * DD + d] = v;
    g_state_rt[((size_t)(row >> 7) * 16 + (d >> 5)) * PANEL_F + swzf(row & 127, d & 31)] =
        f2tf32f(v);
    float ss = v * v;
#pragma unroll
    for (int o = 16; o; o >>= 1) ss += __shfl_xor_sync(0xffffffffu, ss, o);
    if (lane == 0) red[wrp] = ss;
    __syncthreads();
    if (d == 0) {
        float tot = 0.f;
#pragma unroll
        for (int i = 0; i < 16; i++) tot += red[i];
        g_ssq[row] = tot;
        g_shift[row] = sqrtf(tot);
    }
}

__global__ __launch_bounds__(256) void pack_kernel(float* __restrict__ out, int total) {
    int i = blockIdx.x * 256 + threadIdx.x;
    if (i >= total) return;
    if (i < BQ * DD) {
        out[i] = g_state[i];
    } else {
        int e = i - BQ * DD;
        if (e < (NSTEPS + 1) * BQ) out[i] = g_energy[e];
    }
}

// =================================================================
// launch
// =================================================================
extern "C" void kernel_launch(void* const* d_in, const int* in_sizes, int n_in,
                              void* d_out, int out_size) {
    const float* query = (const float*)d_in[0];
    const float* patterns = (const float*)d_in[1];
    if (n_in >= 2 && in_sizes[0] != BQ * DD) {
        const float* t = query;
        query = patterns;
        patterns = t;
    }
    float* out = (float*)d_out;

    cudaFuncSetAttribute(gemm_ms, cudaFuncAttributeMaxDynamicSharedMemorySize, SMEM_BYTES);

    init_state_kernel<<<BQ, 512>>>(query);
    pat_prep_kernel<<<dim3(NP / 32, DD / 32), 256>>>(patterns);

    dim3 g1grid(NP / BN, BQ / BM, 1);        // (512, 8, 1)
    dim3 g2grid(DD / BN, BQ / BM, KSPLIT);   // (4, 8, 64)

    for (int t = 0; t < NSTEPS; t++) {
        gemm_ms<<<g1grid, 256, SMEM_BYTES>>>(0);
        lsum_energy_kernel<<<BQ, 256>>>(t);
        gemm_ms<<<g2grid, 256, SMEM_BYTES>>>(1);
        combine_kernel<<<BQ, 512>>>();
    }
    gemm_ms<<<g1grid, 256, SMEM_BYTES>>>(0);
    lsum_energy_kernel<<<BQ, 256>>>(NSTEPS);

    pack_kernel<<<(out_size + 255) / 256, 256>>>(out, out_size);
}

// round 9
// speedup vs baseline: 3.7159x; 1.7436x over previous
#include <cuda_runtime.h>
#include <cuda_fp16.h>
#include <stdint.h>

#define BQ 1024
#define DD 512
#define NP 65536
#define NSTEPS 10
#define KSPLIT 64

#define BM 128
#define BN 128
#define BK 64
#define PANEL_H 8192                       // halves per 128x64 fp16 panel
#define PANEL_B 16384                      // bytes per panel
#define NSTG 3
#define SMEM_BYTES (1024 + NSTG * 2 * PANEL_B)  // 99328 -> 2 CTAs/SM

// ---------------- tiled global scratch (device globals; no allocation) ----------------
// fp16 panel [128 r][64 cl], SW128: half index = r*64 + (((cl>>1) ^ ((r&7)<<2))<<1) + (cl&1)
__device__ __half g_S_h[(size_t)8 * 1024 * PANEL_H];     // weights tiled [mblk][kstg] 134MB
__device__ __half g_patt_h[(size_t)512 * 8 * PANEL_H];   // P tiled [nblk][dstg]        67MB
__device__ __half g_pattT_h[(size_t)4 * 1024 * PANEL_H]; // P^T tiled [jblk][nstg]      67MB
__device__ __half g_state_ht[(size_t)8 * 8 * PANEL_H];   // fp16(state/b) tiled          1MB
__device__ float g_state[BQ * DD];                       // fp32 state (output)
__device__ float g_lpart[(size_t)BQ * (NP / BN)];        // per-tile weight sums
__device__ float g_rl[BQ];                               // sum of scaled weights
__device__ float g_ssq[BQ];
__device__ float g_ea[BQ];                               // b = ||state||
__device__ float g_eb[BQ];                               // k*ln2 - b  (k = floor(b/ln2))
__device__ float g_energy[(NSTEPS + 1) * BQ];
__device__ float g_part[(size_t)KSPLIT * BQ * DD];       // GEMM2 split-K partials 128MB

// ---------------- helpers ----------------
__device__ __forceinline__ uint32_t swzh(uint32_t r, uint32_t cl) {
    return r * 64u + ((((cl >> 1) ^ ((r & 7u) << 2)) << 1)) + (cl & 1u);
}
__device__ __forceinline__ void mbar_init(uint32_t addr, uint32_t cnt) {
    asm volatile("mbarrier.init.shared.b64 [%0], %1;" ::"r"(addr), "r"(cnt) : "memory");
}
__device__ __forceinline__ void mbar_expect_tx(uint32_t addr, uint32_t bytes) {
    asm volatile("mbarrier.arrive.expect_tx.shared.b64 _, [%0], %1;"
                 ::"r"(addr), "r"(bytes) : "memory");
}
__device__ __forceinline__ void mbar_wait(uint32_t addr, uint32_t parity) {
    asm volatile(
        "{\n\t.reg .pred P1;\n\t"
        "WAIT_%=:\n\t"
        "mbarrier.try_wait.parity.acquire.cta.shared::cta.b64 P1, [%0], %1, 0x989680;\n\t"
        "@!P1 bra WAIT_%=;\n\t"
        "}"
        ::"r"(addr), "r"(parity) : "memory");
}
__device__ __forceinline__ void bulk_g2s(uint32_t daddr, const void* src, uint32_t bytes,
                                         uint32_t mbar) {
    asm volatile(
        "cp.async.bulk.shared::cluster.global.mbarrier::complete_tx::bytes "
        "[%0], [%1], %2, [%3];"
        ::"r"(daddr), "l"(src), "r"(bytes), "r"(mbar) : "memory");
}

// =================================================================
// Unified fp16 mma.sync GEMM over tiled panels (fp32 accum).
// which=0: acc = (state/b)  * P^T  over D=512 (8 stages)
//          epilogue: w' = exp(b*acc + (k ln2 - b)), fp16 store to g_S_h,
//          per-row tile sums of fp16-rounded w' -> g_lpart
// which=1: part[z] = W * P  over 1024 n per split (16 stages); fp32 store
// =================================================================
__global__ __launch_bounds__(256, 2) void gemm_ms(int which) {
    extern __shared__ float sm[];
    const uint32_t sbase = (uint32_t)__cvta_generic_to_shared(sm);

    const __half *A, *B;
    int nit;
    size_t kstg_tot, kb;
    if (which == 0) {
        A = g_state_ht; B = g_patt_h;
        kstg_tot = 8; kb = 0; nit = 8;
    } else {
        A = g_S_h; B = g_pattT_h;
        kstg_tot = 1024; kb = (size_t)blockIdx.z * 16; nit = 16;
    }

    const int tid = threadIdx.x;
    const int wid = tid >> 5, lane = tid & 31;
    const int wm = wid >> 2, wn = wid & 3;  // warp tile 64(M) x 32(N)
    const int g = lane >> 2, c = lane & 3;
    const int bx = blockIdx.x, by = blockIdx.y;

    if (tid == 0) {
#pragma unroll
        for (int b = 0; b < NSTG; b++) mbar_init(sbase + 8 * b, 1);
        asm volatile("fence.proxy.async.shared::cta;" ::: "memory");
    }
    __syncthreads();

    auto stage = [&](int u) {
        int b = u % NSTG;
        uint32_t mbar = sbase + 8 * b;
        uint32_t da = sbase + 1024 + b * (2 * PANEL_B);
        mbar_expect_tx(mbar, 2 * PANEL_B);
        bulk_g2s(da, A + ((size_t)by * kstg_tot + kb + u) * PANEL_H, PANEL_B, mbar);
        bulk_g2s(da + PANEL_B, B + ((size_t)bx * kstg_tot + kb + u) * PANEL_H, PANEL_B, mbar);
    };

    if (tid == 0) {
        stage(0); stage(1); stage(2);
    }

    float acc[4][4][4];
#pragma unroll
    for (int i = 0; i < 4; i++)
#pragma unroll
        for (int j = 0; j < 4; j++)
#pragma unroll
            for (int r = 0; r < 4; r++) acc[i][j][r] = 0.f;

    for (int s = 0; s < nit; s++) {
        int b = s % NSTG;
        mbar_wait(sbase + 8 * b, (s / NSTG) & 1);
        const uint32_t* As32 = (const uint32_t*)((const char*)sm + 1024 + b * (2 * PANEL_B));
        const uint32_t* Bs32 = As32 + PANEL_B / 4;
#pragma unroll
        for (int kk = 0; kk < 4; kk++) {
            const int x0 = (8 * kk + c) ^ (g << 2);
            const int x1 = (8 * kk + c + 4) ^ (g << 2);
            uint32_t af[4][4], bf[4][2];
#pragma unroll
            for (int mi = 0; mi < 4; mi++) {
                int r0 = wm * 64 + mi * 16 + g;
                af[mi][0] = As32[r0 * 32 + x0];
                af[mi][1] = As32[(r0 + 8) * 32 + x0];
                af[mi][2] = As32[r0 * 32 + x1];
                af[mi][3] = As32[(r0 + 8) * 32 + x1];
            }
#pragma unroll
            for (int ni = 0; ni < 4; ni++) {
                int nr = wn * 32 + ni * 8 + g;
                bf[ni][0] = Bs32[nr * 32 + x0];
                bf[ni][1] = Bs32[nr * 32 + x1];
            }
#pragma unroll
            for (int mi = 0; mi < 4; mi++)
#pragma unroll
                for (int ni = 0; ni < 4; ni++) {
                    asm volatile(
                        "mma.sync.aligned.m16n8k16.row.col.f32.f16.f16.f32 "
                        "{%0,%1,%2,%3}, {%4,%5,%6,%7}, {%8,%9}, {%0,%1,%2,%3};\n"
                        : "+f"(acc[mi][ni][0]), "+f"(acc[mi][ni][1]),
                          "+f"(acc[mi][ni][2]), "+f"(acc[mi][ni][3])
                        : "r"(af[mi][0]), "r"(af[mi][1]), "r"(af[mi][2]), "r"(af[mi][3]),
                          "r"(bf[ni][0]), "r"(bf[ni][1]));
                }
        }
        __syncthreads();
        if (tid == 0 && s + NSTG < nit) stage(s + NSTG);
    }

    if (which == 0) {
        // ---- epilogue: w' = exp(b*acc + cb), fp16 store + row sums ----
        __half* Sp = g_S_h + ((size_t)by * 1024 + bx * 2 + (wn >> 1)) * PANEL_H;
        float* lsum = sm + 256;  // [128][4]; staging buffers are dead now
#pragma unroll
        for (int mi = 0; mi < 4; mi++) {
            int r0 = wm * 64 + mi * 16 + g;
            float bb0 = g_ea[by * BM + r0], cb0 = g_eb[by * BM + r0];
            float bb1 = g_ea[by * BM + r0 + 8], cb1 = g_eb[by * BM + r0 + 8];
            float s0 = 0.f, s1 = 0.f;
#pragma unroll
            for (int ni = 0; ni < 4; ni++) {
                int cl = (wn & 1) * 32 + ni * 8 + 2 * c;
                __half h00 = __float2half_rn(__expf(fmaf(bb0, acc[mi][ni][0], cb0)));
                __half h01 = __float2half_rn(__expf(fmaf(bb0, acc[mi][ni][1], cb0)));
                __half h10 = __float2half_rn(__expf(fmaf(bb1, acc[mi][ni][2], cb1)));
                __half h11 = __float2half_rn(__expf(fmaf(bb1, acc[mi][ni][3], cb1)));
                s0 += __half2float(h00) + __half2float(h01);
                s1 += __half2float(h10) + __half2float(h11);
                *(__half2*)&Sp[swzh(r0, cl)] = __halves2half2(h00, h01);
                *(__half2*)&Sp[swzh(r0 + 8, cl)] = __halves2half2(h10, h11);
            }
            s0 += __shfl_xor_sync(0xffffffffu, s0, 1);
            s0 += __shfl_xor_sync(0xffffffffu, s0, 2);
            s1 += __shfl_xor_sync(0xffffffffu, s1, 1);
            s1 += __shfl_xor_sync(0xffffffffu, s1, 2);
            if (c == 0) {
                lsum[r0 * 4 + wn] = s0;
                lsum[(r0 + 8) * 4 + wn] = s1;
            }
        }
        __syncthreads();
        if (tid < 128) {
            float tot = lsum[tid * 4 + 0] + lsum[tid * 4 + 1] +
                        lsum[tid * 4 + 2] + lsum[tid * 4 + 3];
            g_lpart[(size_t)(by * BM + tid) * (NP / BN) + bx] = tot;
        }
    } else {
        float* Dp = g_part + (size_t)blockIdx.z * (BQ * DD) +
                    (size_t)(by * BM) * DD + bx * BN;
#pragma unroll
        for (int mi = 0; mi < 4; mi++) {
            int r0 = wm * 64 + mi * 16 + g;
#pragma unroll
            for (int ni = 0; ni < 4; ni++) {
                int col = wn * 32 + ni * 8 + c * 2;
                float2 v0 = make_float2(acc[mi][ni][0], acc[mi][ni][1]);
                float2 v1 = make_float2(acc[mi][ni][2], acc[mi][ni][3]);
                *(float2*)&Dp[(size_t)r0 * DD + col] = v0;
                *(float2*)&Dp[(size_t)(r0 + 8) * DD + col] = v1;
            }
        }
    }
}

// =================================================================
// Pattern prep (once): fp16 into tiled g_patt_h and g_pattT_h
// block: 64n x 64d tile, 256 threads
// =================================================================
__global__ __launch_bounds__(256) void pat_prep_kernel(const float* __restrict__ pat) {
    __shared__ float t[64][65];
    int n0 = blockIdx.x * 64, d0 = blockIdx.y * 64;
    int tid = threadIdx.x;
#pragma unroll
    for (int j = 0; j < 16; j++) {
        int i = tid + j * 256;
        int nl = i >> 6, dl = i & 63;
        t[nl][dl] = pat[(size_t)(n0 + nl) * DD + d0 + dl];
    }
    __syncthreads();
    // patt_h: [nblk][dstg] panels [128 n][64 d]
#pragma unroll
    for (int j = 0; j < 8; j++) {
        int i = tid + j * 256;
        int nl = i >> 5, pc = i & 31;  // d pair
        int n = n0 + nl;
        __half2 v = __floats2half2_rn(t[nl][2 * pc], t[nl][2 * pc + 1]);
        size_t panel = (size_t)(n >> 7) * 8 + (d0 >> 6);
        *(__half2*)&g_patt_h[panel * PANEL_H + swzh(n & 127, 2 * pc)] = v;
    }
    // pattT_h: [jblk][nstg] panels [128 j(d)][64 n]
#pragma unroll
    for (int j = 0; j < 8; j++) {
        int i = tid + j * 256;
        int dl = i >> 5, pc = i & 31;  // n pair
        int d = d0 + dl;
        __half2 v = __floats2half2_rn(t[2 * pc][dl], t[2 * pc + 1][dl]);
        size_t panel = (size_t)(d >> 7) * 1024 + (n0 >> 6);
        *(__half2*)&g_pattT_h[panel * PANEL_H + swzh(d & 127, 2 * pc)] = v;
    }
}

// =================================================================
// lsum + energy: l = sum of 512 tile sums; E = cb - log l + 0.5 ssq
// =================================================================
__global__ __launch_bounds__(256) void lsum_energy_kernel(int step) {
    const int row = blockIdx.x;
    const int tid = threadIdx.x;
    const int lane = tid & 31, wrp = tid >> 5;
    __shared__ float red[8];
    float s = 0.f;
    for (int k = tid; k < NP / BN; k += 256) s += g_lpart[(size_t)row * (NP / BN) + k];
#pragma unroll
    for (int o = 16; o; o >>= 1) s += __shfl_xor_sync(0xffffffffu, s, o);
    if (lane == 0) red[wrp] = s;
    __syncthreads();
    if (tid == 0) {
        float l = 0.f;
#pragma unroll
        for (int i = 0; i < 8; i++) l += red[i];
        g_rl[row] = l;
        g_energy[step * BQ + row] = g_eb[row] - logf(l) + 0.5f * g_ssq[row];
    }
}

// =================================================================
// Combine: state = (sum partials) / l; then write fp16(state/b) tiled;
// set ssq, b, k-coefs. One block per row, 512 threads.
// =================================================================
__global__ __launch_bounds__(512) void combine_kernel() {
    const int row = blockIdx.x;
    const int d = threadIdx.x;
    const int lane = d & 31, wrp = d >> 5;
    __shared__ float red[16];
    __shared__ float sh_invb;
    float s = 0.f;
#pragma unroll
    for (int z = 0; z < KSPLIT; z++)
        s += g_part[(size_t)z * (BQ * DD) + (size_t)row * DD + d];
    float v = s / g_rl[row];
    g_state[(size_t)row * DD + d] = v;
    float ss = v * v;
#pragma unroll
    for (int o = 16; o; o >>= 1) ss += __shfl_xor_sync(0xffffffffu, ss, o);
    if (lane == 0) red[wrp] = ss;
    __syncthreads();
    if (d == 0) {
        float tot = 0.f;
#pragma unroll
        for (int i = 0; i < 16; i++) tot += red[i];
        float b = sqrtf(tot);
        float k = floorf(b * 1.44269504f);
        g_ssq[row] = tot;
        g_ea[row] = b;
        g_eb[row] = k * 0.69314718056f - b;
        sh_invb = 1.0f / b;
    }
    __syncthreads();
    __half hv = __float2half_rn(v * sh_invb);
    g_state_ht[((size_t)(row >> 7) * 8 + (d >> 6)) * PANEL_H + swzh(row & 127, d & 63)] = hv;
}

__global__ __launch_bounds__(512) void init_state_kernel(const float* __restrict__ q) {
    const int row = blockIdx.x;
    const int d = threadIdx.x;
    const int lane = d & 31, wrp = d >> 5;
    __shared__ float red[16];
    __shared__ float sh_invb;
    float v = q[(size_t)row * DD + d];
    g_state[(size_t)row * DD + d] = v;
    float ss = v * v;
#pragma unroll
    for (int o = 16; o; o >>= 1) ss += __shfl_xor_sync(0xffffffffu, ss, o);
    if (lane == 0) red[wrp] = ss;
    __syncthreads();
    if (d == 0) {
        float tot = 0.f;
#pragma unroll
        for (int i = 0; i < 16; i++) tot += red[i];
        float b = sqrtf(tot);
        float k = floorf(b * 1.44269504f);
        g_ssq[row] = tot;
        g_ea[row] = b;
        g_eb[row] = k * 0.69314718056f - b;
        sh_invb = 1.0f / b;
    }
    __syncthreads();
    __half hv = __float2half_rn(v * sh_invb);
    g_state_ht[((size_t)(row >> 7) * 8 + (d >> 6)) * PANEL_H + swzh(row & 127, d & 63)] = hv;
}

__global__ __launch_bounds__(256) void pack_kernel(float* __restrict__ out, int total) {
    int i = blockIdx.x * 256 + threadIdx.x;
    if (i >= total) return;
    if (i < BQ * DD) {
        out[i] = g_state[i];
    } else {
        int e = i - BQ * DD;
        if (e < (NSTEPS + 1) * BQ) out[i] = g_energy[e];
    }
}

// =================================================================
// launch
// =================================================================
extern "C" void kernel_launch(void* const* d_in, const int* in_sizes, int n_in,
                              void* d_out, int out_size) {
    const float* query = (const float*)d_in[0];
    const float* patterns = (const float*)d_in[1];
    if (n_in >= 2 && in_sizes[0] != BQ * DD) {
        const float* t = query;
        query = patterns;
        patterns = t;
    }
    float* out = (float*)d_out;

    cudaFuncSetAttribute(gemm_ms, cudaFuncAttributeMaxDynamicSharedMemorySize, SMEM_BYTES);

    init_state_kernel<<<BQ, 512>>>(query);
    pat_prep_kernel<<<dim3(NP / 64, DD / 64), 256>>>(patterns);

    dim3 g1grid(NP / BN, BQ / BM, 1);        // (512, 8, 1)
    dim3 g2grid(DD / BN, BQ / BM, KSPLIT);   // (4, 8, 64)

    for (int t = 0; t < NSTEPS; t++) {
        gemm_ms<<<g1grid, 256, SMEM_BYTES>>>(0);
        lsum_energy_kernel<<<BQ, 256>>>(t);
        gemm_ms<<<g2grid, 256, SMEM_BYTES>>>(1);
        combine_kernel<<<BQ, 512>>>();
    }
    gemm_ms<<<g1grid, 256, SMEM_BYTES>>>(0);
    lsum_energy_kernel<<<BQ, 256>>>(NSTEPS);

    pack_kernel<<<(out_size + 255) / 256, 256>>>(out, out_size);
}